// round 3
// baseline (speedup 1.0000x reference)
#include <cuda_runtime.h>
#include <cstdint>

#define B 8
#define N 100000
#define V 40
#define NBINS (V * V * V)            // 64000
#define NTILES 63
#define TILE 1024
#define PB_F  (NBINS * 81)           // 5,184,000 floats per batch
#define PB_F4 (PB_F / 4)             // 1,296,000 float4 per batch

// Output layout (float32 elements):
#define O_IDX  0
#define O_HASH 800000
#define O_NBR  1600000
#define O_MASK 43072000

// neighbour-table work blocks (256 float4-of-q per block, each stored to 8 batches)
#define NBR_TOTAL 5063               // ceil(PB_F4 / 256)
#define NB_BIN 1100
#define NB_SA  500
#define NB_SB  400
#define NB_SC  500
#define NB_SCT 1500
#define NB_FIN 1063                  // sum = 5063

// chain block counts
#define CB_BIN  3125                 // ceil(B*N/256)
#define CB_SA   (B * NTILES)         // 504
#define CB_SB   1
#define CB_SC   (B * NTILES)         // 504
#define CB_SCT  1563                 // ceil(B*N/2/256)
#define CB_FIN  2000                 // B*NBINS/256

// ---- scratch (device globals; zero-initialized at load) ----
__device__ int g_voxel[B * N];
__device__ int g_hist[B * NBINS];    // counts -> offsets (in place); re-zeroed by finalize
__device__ int g_cursor[B * NBINS];
__device__ int g_sorted[B * N];
__device__ int g_tsum[B * NTILES];

// ---------------------------------------------------------------------------
// neighbour-table slice writer: one thread = one float4 of batch-0 layout,
// stored to all 8 batches. qb = global 256-wide q-block index.
__device__ __forceinline__ void nbr_write(float* __restrict__ out, int qb) {
    int q = qb * 256 + threadIdx.x;
    if (q >= PB_F4) return;
    int e0  = q * 4;
    int vox = e0 / 81;
    int j0  = e0 - vox * 81;
    int x = vox / (V * V);
    int r = vox - x * (V * V);
    int y = r / V;
    int z = r - y * V;
    // coords of vox+1 for float4s that straddle a voxel boundary
    int zn = z + 1, yn = y, xn = x;
    if (zn == V) { zn = 0; yn = y + 1; if (yn == V) { yn = 0; xn = x + 1; } }
    float c0[3] = { (float)x,  (float)y,  (float)z  };
    float c1[3] = { (float)xn, (float)yn, (float)zn };

    float4 v;
    float* vp = &v.x;
    #pragma unroll
    for (int k = 0; k < 4; k++) {
        int jk = j0 + k;
        bool w = jk >= 81;
        int jj = w ? jk - 81 : jk;
        int m = jj / 3;
        int c = jj - m * 3;
        int d;
        if (c == 0)      d = m / 9 - 1;
        else if (c == 1) d = (m / 3) % 3 - 1;
        else             d = m % 3 - 1;
        vp[k] = (w ? c1[c] : c0[c]) + (float)d;
    }

    float4* pout = (float4*)(out + O_NBR);
    #pragma unroll
    for (int b = 0; b < B; b++) pout[q + b * PB_F4] = v;
}

// ---------------------------------------------------------------------------
__global__ void bin_kernel(const float* __restrict__ pts, float* __restrict__ out) {
    if (blockIdx.x >= CB_BIN) { nbr_write(out, blockIdx.x - CB_BIN); return; }
    int i = blockIdx.x * blockDim.x + threadIdx.x;
    if (i >= B * N) return;
    int b = i / N;
    const float* p = pts + (size_t)i * 3;
    int cx = (int)(p[0] * (float)(V - 1));
    int cy = (int)(p[1] * (float)(V - 1));
    int cz = (int)(p[2] * (float)(V - 1));
    int bin = cx * (V * V) + cy * V + cz;
    g_voxel[i] = bin;
    atomicAdd(&g_hist[b * NBINS + bin], 1);
}

// Phase A: per-tile sums.
__global__ void scanA_kernel(float* __restrict__ out) {
    if (blockIdx.x >= CB_SA) { nbr_write(out, NB_BIN + blockIdx.x - CB_SA); return; }
    int b = blockIdx.x / NTILES;
    int t = blockIdx.x % NTILES;
    int tb = t * TILE + threadIdx.x * 4;
    int s = 0;
    if (tb < NBINS) {
        int4 v = *(const int4*)(g_hist + b * NBINS + tb);
        s = v.x + v.y + v.z + v.w;
    }
    #pragma unroll
    for (int o = 16; o > 0; o >>= 1) s += __shfl_down_sync(0xFFFFFFFFu, s, o);
    __shared__ int ws[8];
    int lane = threadIdx.x & 31, warp = threadIdx.x >> 5;
    if (lane == 0) ws[warp] = s;
    __syncthreads();
    if (threadIdx.x == 0) {
        int tot = 0;
        #pragma unroll
        for (int w = 0; w < 8; w++) tot += ws[w];
        g_tsum[b * NTILES + t] = tot;
    }
}

// Phase B: exclusive scan of 63 tile sums per batch (one warp per batch).
__global__ void scanB_kernel(float* __restrict__ out) {
    if (blockIdx.x >= CB_SB) { nbr_write(out, NB_BIN + NB_SA + blockIdx.x - CB_SB); return; }
    int w = threadIdx.x >> 5, lane = threadIdx.x & 31;
    if (w >= B) return;
    int* ts = g_tsum + w * NTILES;
    int v0 = ts[lane];
    int v1 = (lane < NTILES - 32) ? ts[32 + lane] : 0;
    int s0 = v0, s1 = v1;
    #pragma unroll
    for (int o = 1; o < 32; o <<= 1) {
        int t0 = __shfl_up_sync(0xFFFFFFFFu, s0, o);
        int t1 = __shfl_up_sync(0xFFFFFFFFu, s1, o);
        if (lane >= o) { s0 += t0; s1 += t1; }
    }
    int tot0 = __shfl_sync(0xFFFFFFFFu, s0, 31);
    ts[lane] = s0 - v0;
    if (lane < NTILES - 32) ts[32 + lane] = tot0 + s1 - v1;
}

// Phase C: rescan each tile with its base; write offsets + cursors.
__global__ void scanC_kernel(float* __restrict__ out) {
    if (blockIdx.x >= CB_SC) { nbr_write(out, NB_BIN + NB_SA + NB_SB + blockIdx.x - CB_SC); return; }
    int b = blockIdx.x / NTILES;
    int t = blockIdx.x % NTILES;
    int tb = t * TILE + threadIdx.x * 4;
    int4 v = make_int4(0, 0, 0, 0);
    if (tb < NBINS) v = *(const int4*)(g_hist + b * NBINS + tb);
    int tsum = v.x + v.y + v.z + v.w;
    int lane = threadIdx.x & 31, warp = threadIdx.x >> 5;
    int x = tsum;
    #pragma unroll
    for (int o = 1; o < 32; o <<= 1) {
        int tt = __shfl_up_sync(0xFFFFFFFFu, x, o);
        if (lane >= o) x += tt;
    }
    __shared__ int ws[8];
    if (lane == 31) ws[warp] = x;
    __syncthreads();
    int woff = 0;
    #pragma unroll
    for (int w = 0; w < 8; w++) woff += (w < warp) ? ws[w] : 0;
    int base = g_tsum[b * NTILES + t] + woff + x - tsum;
    if (tb < NBINS) {
        int4 o4;
        o4.x = base;
        o4.y = base + v.x;
        o4.z = base + v.x + v.y;
        o4.w = base + v.x + v.y + v.z;
        *(int4*)(g_hist + b * NBINS + tb) = o4;
        *(int4*)(g_cursor + b * NBINS + tb) = o4;
    }
}

// scatter: 2 points per thread.
__global__ void scatter_kernel(float* __restrict__ out) {
    if (blockIdx.x >= CB_SCT) {
        nbr_write(out, NB_BIN + NB_SA + NB_SB + NB_SC + blockIdx.x - CB_SCT);
        return;
    }
    int t = blockIdx.x * blockDim.x + threadIdx.x;
    #pragma unroll
    for (int k = 0; k < 2; k++) {
        int i = t * 2 + k;
        if (i < B * N) {
            int b = i / N;
            int n = i - b * N;
            int bin = g_voxel[i];
            int pos = atomicAdd(&g_cursor[b * NBINS + bin], 1);
            g_sorted[b * N + pos] = n;
        }
    }
}

// finalize: stable fixup + idx/hash/mask writes; restores g_hist zeros.
__global__ void finalize_kernel(float* __restrict__ out) {
    if (blockIdx.x >= CB_FIN) {
        nbr_write(out, NB_BIN + NB_SA + NB_SB + NB_SC + NB_SCT + blockIdx.x - CB_FIN);
        return;
    }
    int t = blockIdx.x * blockDim.x + threadIdx.x;
    int b = t / NBINS;
    int bin = t - b * NBINS;
    int s = g_hist[b * NBINS + bin];
    int e = g_cursor[b * NBINS + bin];      // post-scatter cursor == segment end
    g_hist[b * NBINS + bin] = 0;            // restore invariant for next replay
    int* seg = g_sorted + b * N;

    for (int a = s + 1; a < e; a++) {       // bins are tiny (Poisson mean ~1.6)
        int key = seg[a];
        int j = a - 1;
        while (j >= s && seg[j] > key) { seg[j + 1] = seg[j]; j--; }
        seg[j + 1] = key;
    }

    int cx = bin / (V * V);
    int cy = (bin / V) % V;
    int cz = bin % V;
    float h = (float)(cx * 10000 + cy * 100 + cz);
    for (int j = s; j < e; j++) {
        out[O_IDX  + b * N + j] = (float)seg[j];
        out[O_HASH + b * N + j] = h;
    }
    out[O_MASK + b * NBINS + bin] = (e > s && e < N) ? 1.0f : 0.0f;
}

// ---------------------------------------------------------------------------
extern "C" void kernel_launch(void* const* d_in, const int* in_sizes, int n_in,
                              void* d_out, int out_size) {
    const float* pts = (const float*)d_in[0];
    float* out = (float*)d_out;

    bin_kernel     <<<CB_BIN + NB_BIN, 256>>>(pts, out);
    scanA_kernel   <<<CB_SA  + NB_SA,  256>>>(out);
    scanB_kernel   <<<CB_SB  + NB_SB,  256>>>(out);
    scanC_kernel   <<<CB_SC  + NB_SC,  256>>>(out);
    scatter_kernel <<<CB_SCT + NB_SCT, 256>>>(out);
    finalize_kernel<<<CB_FIN + NB_FIN, 256>>>(out);
}